// round 14
// baseline (speedup 1.0000x reference)
#include <cuda_runtime.h>
#include <cuda_bf16.h>

#define HID 256
#define GAMMA_F 12.0f
#define BATCH 8
#define NE_MAX 100000

typedef unsigned long long u64;

__device__ float g_scores[BATCH * NE_MAX];   // S[e*8+b], 3.2MB (L2-resident)

__device__ __forceinline__ u64 ffma2(u64 a, u64 b, u64 c) {
    u64 d;
    asm("fma.rn.f32x2 %0, %1, %2, %3;" : "=l"(d) : "l"(a), "l"(b), "l"(c));
    return d;
}
__device__ __forceinline__ u64 fadd2(u64 a, u64 b) {
    u64 d;
    asm("add.rn.f32x2 %0, %1, %2;" : "=l"(d) : "l"(a), "l"(b));
    return d;
}
__device__ __forceinline__ u64 pack2(float lo, float hi) {
    u64 d;
    asm("mov.b64 %0, {%1, %2};" : "=l"(d) : "f"(lo), "f"(hi));
    return d;
}
__device__ __forceinline__ float2 unpack2(u64 v) {
    float2 r;
    asm("mov.b64 {%0, %1}, %2;" : "=f"(r.x), "=f"(r.y) : "l"(v));
    return r;
}

#define ABSMASK2 0x7FFFFFFF7FFFFFFFULL
#define NEG2X2   0xC0000000C0000000ULL   // (-2.0f, -2.0f)

// ---------------------------------------------------------------------------
// Phase 1: warp per contiguous chunk; 2 rows/iter + 2-row lookahead.
// hr2[j] on lane l = packed 2*(head+rel) of batch (j ^ perm(l)), perm=(l>>2)&7
// -> every fold stage is a pure SHFL+FADD. Packed f32x2 inner math.
// ---------------------------------------------------------------------------
__global__ void __launch_bounds__(256, 2)
score_kernel(const float* __restrict__ ent,
             const float* __restrict__ rel,
             const int*   __restrict__ pos,
             float*       __restrict__ scores,
             int ne)
{
    const int lane = threadIdx.x & 31;
    const int warp = threadIdx.x >> 5;
    const int perm = (lane >> 2) & 7;

    // hr2[j][p] = packed dims (p*2, p*2+1) of lane's 8, batch j^perm. 64 regs.
    u64 hr2[BATCH][4];
#pragma unroll
    for (int j = 0; j < BATCH; j++) {
        const int b = j ^ perm;
        const int hidx = pos[b * 3 + 0];
        const int ridx = pos[b * 3 + 1];
        const float4* h4 = reinterpret_cast<const float4*>(ent + (size_t)hidx * HID);
        const float4* r4 = reinterpret_cast<const float4*>(rel + (size_t)ridx * HID);
        float4 h0 = h4[lane * 2], h1 = h4[lane * 2 + 1];
        float4 r0 = r4[lane * 2], r1 = r4[lane * 2 + 1];
        hr2[j][0] = pack2(2.0f * (h0.x + r0.x), 2.0f * (h0.y + r0.y));
        hr2[j][1] = pack2(2.0f * (h0.z + r0.z), 2.0f * (h0.w + r0.w));
        hr2[j][2] = pack2(2.0f * (h1.x + r1.x), 2.0f * (h1.y + r1.y));
        hr2[j][3] = pack2(2.0f * (h1.z + r1.z), 2.0f * (h1.w + r1.w));
    }

    // Contiguous chunk per warp.
    const int gw = blockIdx.x * 8 + warp;
    const int W  = gridDim.x * 8;
    const int per   = ne / W;
    const int rem   = ne % W;
    const int start = gw * per + (gw < rem ? gw : rem);
    const int end   = start + per + (gw < rem ? 1 : 0);

    u64 eA[4], eB[4], pA[4], pB[4];

    auto ld = [&](int row, u64* d) {
        const ulonglong2* er = reinterpret_cast<const ulonglong2*>(ent + (size_t)row * HID);
        ulonglong2 x = er[lane * 2], y = er[lane * 2 + 1];
        d[0] = x.x; d[1] = x.y; d[2] = y.x; d[3] = y.y;
    };

    if (start     < end) ld(start, eA);
    if (start + 1 < end) ld(start + 1, eB);

    for (int row = start; row < end; row += 2) {
        const bool hasB = row + 1 < end;
        if (row + 2 < end) ld(row + 2, pA);   // lookahead
        if (row + 3 < end) ld(row + 3, pB);

        float vA[BATCH], vB[BATCH];
#pragma unroll
        for (int j = 0; j < BATCH; j++) {
            u64 aA = 0, aB = 0;
#pragma unroll
            for (int p = 0; p < 4; p++) {
                const u64 dA = ffma2(eA[p], NEG2X2, hr2[j][p]);  // 2hr - 2e
                const u64 dB = ffma2(eB[p], NEG2X2, hr2[j][p]);
                aA = fadd2(aA, dA & ABSMASK2);                    // += |.| (LOP3 on alu)
                aB = fadd2(aB, dB & ABSMASK2);
            }
            const float2 fa = unpack2(aA);
            const float2 fb = unpack2(aB);
            vA[j] = fa.x + fa.y;
            vB[j] = fb.x + fb.y;
        }

        // FSEL-free folds; A and B chains independent -> overlap.
#pragma unroll
        for (int j = 0; j < 4; j++) {
            vA[j] += __shfl_xor_sync(0xFFFFFFFFu, vA[j + 4], 16);
            vB[j] += __shfl_xor_sync(0xFFFFFFFFu, vB[j + 4], 16);
        }
#pragma unroll
        for (int j = 0; j < 2; j++) {
            vA[j] += __shfl_xor_sync(0xFFFFFFFFu, vA[j + 2], 8);
            vB[j] += __shfl_xor_sync(0xFFFFFFFFu, vB[j + 2], 8);
        }
        vA[0] += __shfl_xor_sync(0xFFFFFFFFu, vA[1], 4);
        vB[0] += __shfl_xor_sync(0xFFFFFFFFu, vB[1], 4);
        vA[0] += __shfl_xor_sync(0xFFFFFFFFu, vA[0], 2);
        vB[0] += __shfl_xor_sync(0xFFFFFFFFu, vB[0], 2);
        vA[0] += __shfl_xor_sync(0xFFFFFFFFu, vA[0], 1);
        vB[0] += __shfl_xor_sync(0xFFFFFFFFu, vB[0], 1);

        // Lane 4k holds the full (doubled) sum for batch k (= perm).
        if ((lane & 3) == 0) {
            scores[(size_t)row * BATCH + perm] = __fmaf_rn(vA[0], -0.5f, GAMMA_F);
            if (hasB)
                scores[(size_t)(row + 1) * BATCH + perm] =
                    __fmaf_rn(vB[0], -0.5f, GAMMA_F);
        }

#pragma unroll
        for (int k = 0; k < 4; k++) { eA[k] = pA[k]; eB[k] = pB[k]; }
    }
}

// ---------------------------------------------------------------------------
// Phase 2: out[b][n] = scores[neg[b][n]*8 + b]. Best-measured config.
// ---------------------------------------------------------------------------
__global__ void __launch_bounds__(128)
gather_kernel(const float* __restrict__ scores,
              const int*   __restrict__ neg,
              float*       __restrict__ out,
              int nneg)
{
    const int b = blockIdx.y;
    const int t = blockIdx.x * 128 + threadIdx.x;
    const int n4 = nneg >> 2;

    if (t < n4) {
        const int4 idx = reinterpret_cast<const int4*>(neg + (size_t)b * nneg)[t];
        float4 r;
        r.x = __ldg(scores + (size_t)idx.x * BATCH + b);
        r.y = __ldg(scores + (size_t)idx.y * BATCH + b);
        r.z = __ldg(scores + (size_t)idx.z * BATCH + b);
        r.w = __ldg(scores + (size_t)idx.w * BATCH + b);
        reinterpret_cast<float4*>(out + (size_t)b * nneg)[t] = r;
    }
    const int tail = nneg - n4 * 4;
    if (blockIdx.x == 0 && threadIdx.x < tail) {
        const int n = n4 * 4 + threadIdx.x;
        out[(size_t)b * nneg + n] =
            __ldg(scores + (size_t)neg[(size_t)b * nneg + n] * BATCH + b);
    }
}

extern "C" void kernel_launch(void* const* d_in, const int* in_sizes, int n_in,
                              void* d_out, int out_size)
{
    const float* ent = (const float*)d_in[0];  // [NE, 256] f32
    const float* rel = (const float*)d_in[1];  // [NR, 256] f32
    const int*   pos = (const int*)d_in[2];    // [B, 3] i32
    const int*   neg = (const int*)d_in[3];    // [B, N] i32
    float*       out = (float*)d_out;          // [B, N] f32

    const int batch = in_sizes[2] / 3;         // 8
    const int nneg  = in_sizes[3] / batch;     // 100000
    const int ne    = in_sizes[0] / HID;       // 100000
    (void)batch;

    float* scores;
    cudaGetSymbolAddress((void**)&scores, g_scores);

    score_kernel<<<296, 256>>>(ent, rel, pos, scores, ne);

    dim3 g2((nneg / 4 + 127) / 128, BATCH);
    gather_kernel<<<g2, 128>>>(scores, neg, out, nneg);
}

// round 15
// speedup vs baseline: 1.1757x; 1.1757x over previous
#include <cuda_runtime.h>
#include <cuda_bf16.h>

#define HID 256
#define GAMMA_F 12.0f
#define BATCH 8
#define NE_MAX 100000

__device__ float g_scores[BATCH * NE_MAX];   // S[e*8+b], 3.2MB (L2-resident)

// acc = |x| * 1.0 + acc  — intended to compile to FFMA-imm (rt1) rather than
// FADD (rt2). fabsf folds into the FFMA source modifier.
__device__ __forceinline__ float accabs(float acc, float x) {
    return __fmaf_rn(fabsf(x), 1.0f, acc);
}

// ---------------------------------------------------------------------------
// Phase 1: warp per contiguous chunk; 2 rows/iter + 2-row lookahead.
// hrs2[j] on lane l = 2*(head+rel) of batch (j ^ perm(l)), perm=(l>>2)&7,
// making every fold stage a pure SHFL+FADD (no FSEL anywhere).
// ---------------------------------------------------------------------------
__global__ void __launch_bounds__(256, 2)
score_kernel(const float* __restrict__ ent,
             const float* __restrict__ rel,
             const int*   __restrict__ pos,
             float*       __restrict__ scores,
             int ne)
{
    const int lane = threadIdx.x & 31;
    const int warp = threadIdx.x >> 5;
    const int perm = (lane >> 2) & 7;

    // hrs2[j] = 2*(head+rel) of batch j^perm, lane's 8 dims (64 regs).
    float hrs2[BATCH][8];
#pragma unroll
    for (int j = 0; j < BATCH; j++) {
        const int b = j ^ perm;
        const int hidx = pos[b * 3 + 0];
        const int ridx = pos[b * 3 + 1];
        const float4* h4 = reinterpret_cast<const float4*>(ent + (size_t)hidx * HID);
        const float4* r4 = reinterpret_cast<const float4*>(rel + (size_t)ridx * HID);
        float4 h0 = h4[lane * 2], h1 = h4[lane * 2 + 1];
        float4 r0 = r4[lane * 2], r1 = r4[lane * 2 + 1];
        hrs2[j][0] = 2.0f * (h0.x + r0.x);  hrs2[j][1] = 2.0f * (h0.y + r0.y);
        hrs2[j][2] = 2.0f * (h0.z + r0.z);  hrs2[j][3] = 2.0f * (h0.w + r0.w);
        hrs2[j][4] = 2.0f * (h1.x + r1.x);  hrs2[j][5] = 2.0f * (h1.y + r1.y);
        hrs2[j][6] = 2.0f * (h1.z + r1.z);  hrs2[j][7] = 2.0f * (h1.w + r1.w);
    }

    // Contiguous chunk per warp.
    const int gw = blockIdx.x * 8 + warp;
    const int W  = gridDim.x * 8;
    const int per   = ne / W;
    const int rem   = ne % W;
    const int start = gw * per + (gw < rem ? gw : rem);
    const int end   = start + per + (gw < rem ? 1 : 0);

    float eA[8], eB[8], pA[8], pB[8];

    auto ld = [&](int row, float* d) {
        const float4* er = reinterpret_cast<const float4*>(ent + (size_t)row * HID);
        float4 x = er[lane * 2], y = er[lane * 2 + 1];
        d[0]=x.x; d[1]=x.y; d[2]=x.z; d[3]=x.w;
        d[4]=y.x; d[5]=y.y; d[6]=y.z; d[7]=y.w;
    };

    if (start     < end) ld(start, eA);
    if (start + 1 < end) ld(start + 1, eB);

    for (int row = start; row < end; row += 2) {
        const bool hasB = row + 1 < end;
        if (row + 2 < end) ld(row + 2, pA);   // lookahead
        if (row + 3 < end) ld(row + 3, pB);

        float vA[BATCH], vB[BATCH];
#pragma unroll
        for (int j = 0; j < BATCH; j++) {
            float a = fabsf(__fmaf_rn(eA[0], -2.0f, hrs2[j][0]));
            float b = fabsf(__fmaf_rn(eB[0], -2.0f, hrs2[j][0]));
#pragma unroll
            for (int k = 1; k < 8; k++) {
                a = accabs(a, __fmaf_rn(eA[k], -2.0f, hrs2[j][k]));  // FFMA-imm x2
                b = accabs(b, __fmaf_rn(eB[k], -2.0f, hrs2[j][k]));
            }
            vA[j] = a;  vB[j] = b;
        }

        // FSEL-free folds; A and B chains independent -> overlap.
#pragma unroll
        for (int j = 0; j < 4; j++) {
            vA[j] += __shfl_xor_sync(0xFFFFFFFFu, vA[j + 4], 16);
            vB[j] += __shfl_xor_sync(0xFFFFFFFFu, vB[j + 4], 16);
        }
#pragma unroll
        for (int j = 0; j < 2; j++) {
            vA[j] += __shfl_xor_sync(0xFFFFFFFFu, vA[j + 2], 8);
            vB[j] += __shfl_xor_sync(0xFFFFFFFFu, vB[j + 2], 8);
        }
        vA[0] += __shfl_xor_sync(0xFFFFFFFFu, vA[1], 4);
        vB[0] += __shfl_xor_sync(0xFFFFFFFFu, vB[1], 4);
        vA[0] += __shfl_xor_sync(0xFFFFFFFFu, vA[0], 2);
        vB[0] += __shfl_xor_sync(0xFFFFFFFFu, vB[0], 2);
        vA[0] += __shfl_xor_sync(0xFFFFFFFFu, vA[0], 1);
        vB[0] += __shfl_xor_sync(0xFFFFFFFFu, vB[0], 1);

        // Lane 4k holds full sum for batch k (= perm).
        if ((lane & 3) == 0) {
            scores[(size_t)row * BATCH + perm] = __fmaf_rn(vA[0], -0.5f, GAMMA_F);
            if (hasB)
                scores[(size_t)(row + 1) * BATCH + perm] =
                    __fmaf_rn(vB[0], -0.5f, GAMMA_F);
        }

#pragma unroll
        for (int k = 0; k < 8; k++) { eA[k] = pA[k]; eB[k] = pB[k]; }
    }
}

// ---------------------------------------------------------------------------
// Phase 2: out[b][n] = scores[neg[b][n]*8 + b]. Best-measured config.
// ---------------------------------------------------------------------------
__global__ void __launch_bounds__(128)
gather_kernel(const float* __restrict__ scores,
              const int*   __restrict__ neg,
              float*       __restrict__ out,
              int nneg)
{
    const int b = blockIdx.y;
    const int t = blockIdx.x * 128 + threadIdx.x;
    const int n4 = nneg >> 2;

    if (t < n4) {
        const int4 idx = reinterpret_cast<const int4*>(neg + (size_t)b * nneg)[t];
        float4 r;
        r.x = __ldg(scores + (size_t)idx.x * BATCH + b);
        r.y = __ldg(scores + (size_t)idx.y * BATCH + b);
        r.z = __ldg(scores + (size_t)idx.z * BATCH + b);
        r.w = __ldg(scores + (size_t)idx.w * BATCH + b);
        reinterpret_cast<float4*>(out + (size_t)b * nneg)[t] = r;
    }
    const int tail = nneg - n4 * 4;
    if (blockIdx.x == 0 && threadIdx.x < tail) {
        const int n = n4 * 4 + threadIdx.x;
        out[(size_t)b * nneg + n] =
            __ldg(scores + (size_t)neg[(size_t)b * nneg + n] * BATCH + b);
    }
}

extern "C" void kernel_launch(void* const* d_in, const int* in_sizes, int n_in,
                              void* d_out, int out_size)
{
    const float* ent = (const float*)d_in[0];  // [NE, 256] f32
    const float* rel = (const float*)d_in[1];  // [NR, 256] f32
    const int*   pos = (const int*)d_in[2];    // [B, 3] i32
    const int*   neg = (const int*)d_in[3];    // [B, N] i32
    float*       out = (float*)d_out;          // [B, N] f32

    const int batch = in_sizes[2] / 3;         // 8
    const int nneg  = in_sizes[3] / batch;     // 100000
    const int ne    = in_sizes[0] / HID;       // 100000
    (void)batch;

    float* scores;
    cudaGetSymbolAddress((void**)&scores, g_scores);

    score_kernel<<<296, 256>>>(ent, rel, pos, scores, ne);

    dim3 g2((nneg / 4 + 127) / 128, BATCH);
    gather_kernel<<<g2, 128>>>(scores, neg, out, nneg);
}

// round 16
// speedup vs baseline: 1.2010x; 1.0215x over previous
#include <cuda_runtime.h>
#include <cuda_bf16.h>

#define HID 256
#define GAMMA_F 12.0f
#define BATCH 8
#define NE_MAX 100000

__device__ float g_scores[BATCH * NE_MAX];   // S[e*8+b], 3.2MB (L2-resident)

// ---------------------------------------------------------------------------
// Phase 1: warp per contiguous chunk; 2 rows/iter + 2-row lookahead.
// hrs2[j] on lane l = 2*(head+rel) of batch (j ^ perm(l)), perm=(l>>2)&7 ->
// every fold stage is a pure SHFL+FADD (no FSEL). The final 3-deep fold tail
// (xor4/xor2/xor1 + store) of each row pair is DEFERRED into the next
// iteration so its SHFL latency hides under the next pair's FFMA block.
// ---------------------------------------------------------------------------
__global__ void __launch_bounds__(256, 2)
score_kernel(const float* __restrict__ ent,
             const float* __restrict__ rel,
             const int*   __restrict__ pos,
             float*       __restrict__ scores,
             int ne)
{
    const int lane = threadIdx.x & 31;
    const int warp = threadIdx.x >> 5;
    const int perm = (lane >> 2) & 7;

    // hrs2[j] = 2*(head+rel) of batch j^perm, lane's 8 dims (64 regs).
    float hrs2[BATCH][8];
#pragma unroll
    for (int j = 0; j < BATCH; j++) {
        const int b = j ^ perm;
        const int hidx = pos[b * 3 + 0];
        const int ridx = pos[b * 3 + 1];
        const float4* h4 = reinterpret_cast<const float4*>(ent + (size_t)hidx * HID);
        const float4* r4 = reinterpret_cast<const float4*>(rel + (size_t)ridx * HID);
        float4 h0 = h4[lane * 2], h1 = h4[lane * 2 + 1];
        float4 r0 = r4[lane * 2], r1 = r4[lane * 2 + 1];
        hrs2[j][0] = 2.0f * (h0.x + r0.x);  hrs2[j][1] = 2.0f * (h0.y + r0.y);
        hrs2[j][2] = 2.0f * (h0.z + r0.z);  hrs2[j][3] = 2.0f * (h0.w + r0.w);
        hrs2[j][4] = 2.0f * (h1.x + r1.x);  hrs2[j][5] = 2.0f * (h1.y + r1.y);
        hrs2[j][6] = 2.0f * (h1.z + r1.z);  hrs2[j][7] = 2.0f * (h1.w + r1.w);
    }

    // Contiguous chunk per warp.
    const int gw = blockIdx.x * 8 + warp;
    const int W  = gridDim.x * 8;
    const int per   = ne / W;
    const int rem   = ne % W;
    const int start = gw * per + (gw < rem ? gw : rem);
    const int end   = start + per + (gw < rem ? 1 : 0);

    float eA[8], eB[8], pA[8], pB[8];

    auto ld = [&](int row, float* d) {
        const float4* er = reinterpret_cast<const float4*>(ent + (size_t)row * HID);
        float4 x = er[lane * 2], y = er[lane * 2 + 1];
        d[0]=x.x; d[1]=x.y; d[2]=x.z; d[3]=x.w;
        d[4]=y.x; d[5]=y.y; d[6]=y.z; d[7]=y.w;
    };

    if (start     < end) ld(start, eA);
    if (start + 1 < end) ld(start + 1, eB);

    // Deferred fold-tail state from the previous row pair.
    float cA0 = 0.f, cA1 = 0.f, cB0 = 0.f, cB1 = 0.f;
    int   prow = -1;
    bool  phasB = false;

    for (int row = start; row < end; row += 2) {
        const bool hasB = row + 1 < end;
        if (row + 2 < end) ld(row + 2, pA);   // lookahead
        if (row + 3 < end) ld(row + 3, pB);

        // ---- Deferred tail of PREVIOUS pair: 3-deep SHFL chain + stores ----
        // Issued early so its latency hides under the FFMA block below.
        if (prow >= 0) {
            cA0 += __shfl_xor_sync(0xFFFFFFFFu, cA1, 4);
            cB0 += __shfl_xor_sync(0xFFFFFFFFu, cB1, 4);
            cA0 += __shfl_xor_sync(0xFFFFFFFFu, cA0, 2);
            cB0 += __shfl_xor_sync(0xFFFFFFFFu, cB0, 2);
            cA0 += __shfl_xor_sync(0xFFFFFFFFu, cA0, 1);
            cB0 += __shfl_xor_sync(0xFFFFFFFFu, cB0, 1);
            if ((lane & 3) == 0) {
                scores[(size_t)prow * BATCH + perm] = __fmaf_rn(cA0, -0.5f, GAMMA_F);
                if (phasB)
                    scores[(size_t)(prow + 1) * BATCH + perm] =
                        __fmaf_rn(cB0, -0.5f, GAMMA_F);
            }
        }

        // ---- FFMA block for current pair ----
        float vA[BATCH], vB[BATCH];
#pragma unroll
        for (int j = 0; j < BATCH; j++) {
            float a = fabsf(__fmaf_rn(eA[0], -2.0f, hrs2[j][0]));
            float b = fabsf(__fmaf_rn(eB[0], -2.0f, hrs2[j][0]));
#pragma unroll
            for (int k = 1; k < 8; k++) {
                a += fabsf(__fmaf_rn(eA[k], -2.0f, hrs2[j][k]));
                b += fabsf(__fmaf_rn(eB[k], -2.0f, hrs2[j][k]));
            }
            vA[j] = a;  vB[j] = b;
        }

        // ---- Fold stages 1+2 (FSEL-free), leave 2 slots for the deferred tail
#pragma unroll
        for (int j = 0; j < 4; j++) {
            vA[j] += __shfl_xor_sync(0xFFFFFFFFu, vA[j + 4], 16);
            vB[j] += __shfl_xor_sync(0xFFFFFFFFu, vB[j + 4], 16);
        }
#pragma unroll
        for (int j = 0; j < 2; j++) {
            vA[j] += __shfl_xor_sync(0xFFFFFFFFu, vA[j + 2], 8);
            vB[j] += __shfl_xor_sync(0xFFFFFFFFu, vB[j + 2], 8);
        }
        cA0 = vA[0];  cA1 = vA[1];
        cB0 = vB[0];  cB1 = vB[1];
        prow = row;  phasB = hasB;

#pragma unroll
        for (int k = 0; k < 8; k++) { eA[k] = pA[k]; eB[k] = pB[k]; }
    }

    // ---- Drain the last pair's tail ----
    if (prow >= 0) {
        cA0 += __shfl_xor_sync(0xFFFFFFFFu, cA1, 4);
        cB0 += __shfl_xor_sync(0xFFFFFFFFu, cB1, 4);
        cA0 += __shfl_xor_sync(0xFFFFFFFFu, cA0, 2);
        cB0 += __shfl_xor_sync(0xFFFFFFFFu, cB0, 2);
        cA0 += __shfl_xor_sync(0xFFFFFFFFu, cA0, 1);
        cB0 += __shfl_xor_sync(0xFFFFFFFFu, cB0, 1);
        if ((lane & 3) == 0) {
            scores[(size_t)prow * BATCH + perm] = __fmaf_rn(cA0, -0.5f, GAMMA_F);
            if (phasB)
                scores[(size_t)(prow + 1) * BATCH + perm] =
                    __fmaf_rn(cB0, -0.5f, GAMMA_F);
        }
    }
}

// ---------------------------------------------------------------------------
// Phase 2: out[b][n] = scores[neg[b][n]*8 + b]. Best-measured config.
// ---------------------------------------------------------------------------
__global__ void __launch_bounds__(128)
gather_kernel(const float* __restrict__ scores,
              const int*   __restrict__ neg,
              float*       __restrict__ out,
              int nneg)
{
    const int b = blockIdx.y;
    const int t = blockIdx.x * 128 + threadIdx.x;
    const int n4 = nneg >> 2;

    if (t < n4) {
        const int4 idx = reinterpret_cast<const int4*>(neg + (size_t)b * nneg)[t];
        float4 r;
        r.x = __ldg(scores + (size_t)idx.x * BATCH + b);
        r.y = __ldg(scores + (size_t)idx.y * BATCH + b);
        r.z = __ldg(scores + (size_t)idx.z * BATCH + b);
        r.w = __ldg(scores + (size_t)idx.w * BATCH + b);
        reinterpret_cast<float4*>(out + (size_t)b * nneg)[t] = r;
    }
    const int tail = nneg - n4 * 4;
    if (blockIdx.x == 0 && threadIdx.x < tail) {
        const int n = n4 * 4 + threadIdx.x;
        out[(size_t)b * nneg + n] =
            __ldg(scores + (size_t)neg[(size_t)b * nneg + n] * BATCH + b);
    }
}

extern "C" void kernel_launch(void* const* d_in, const int* in_sizes, int n_in,
                              void* d_out, int out_size)
{
    const float* ent = (const float*)d_in[0];  // [NE, 256] f32
    const float* rel = (const float*)d_in[1];  // [NR, 256] f32
    const int*   pos = (const int*)d_in[2];    // [B, 3] i32
    const int*   neg = (const int*)d_in[3];    // [B, N] i32
    float*       out = (float*)d_out;          // [B, N] f32

    const int batch = in_sizes[2] / 3;         // 8
    const int nneg  = in_sizes[3] / batch;     // 100000
    const int ne    = in_sizes[0] / HID;       // 100000
    (void)batch;

    float* scores;
    cudaGetSymbolAddress((void**)&scores, g_scores);

    score_kernel<<<296, 256>>>(ent, rel, pos, scores, ne);

    dim3 g2((nneg / 4 + 127) / 128, BATCH);
    gather_kernel<<<g2, 128>>>(scores, neg, out, nneg);
}